// round 4
// baseline (speedup 1.0000x reference)
#include <cuda_runtime.h>
#include <math.h>

#define NN 50000
#define EE 1600000
#define E2T (EE + NN)
#define GG 512

// ---------------- scratch (allocation-free: __device__ globals) ----------------
__device__ float    g_xl1[NN * 100];
__device__ float    g_xr1[NN * 100];
__device__ float    g_out1[NN * 100];
__device__ float    g_xl2[NN * 200];
__device__ float    g_xr2[NN * 200];
__device__ float    g_out2[NN * 200];
__device__ float    g_h3[NN * 400];
__device__ float    g_s[E2T];
__device__ unsigned g_m[NN];
__device__ float    g_z[NN];
__device__ float    g_deg[NN];
__device__ float    g_easum[NN * 18];
__device__ float    g_pool[GG * 400];
__device__ float    g_cnt[GG];
__device__ float    g_y1[GG * 200];
__device__ float    g_y2[GG * 100];

// monotonic float <-> uint map for atomicMax on floats (handles negatives)
__device__ __forceinline__ unsigned fmap(float f) {
    unsigned u = __float_as_uint(f);
    return (u & 0x80000000u) ? ~u : (u | 0x80000000u);
}
__device__ __forceinline__ float funmap(unsigned u) {
    return __uint_as_float((u & 0x80000000u) ? (u & 0x7FFFFFFFu) : ~u);
}

// ---------------- self-loop edge-attr accumulation ----------------
__global__ void k_ea_accum(const int* __restrict__ ei, const float* __restrict__ ea,
                           float* __restrict__ deg, float* __restrict__ easum) {
    int i = blockIdx.x * blockDim.x + threadIdx.x;
    if (i >= EE * 18) return;
    int e = i / 18, k = i - e * 18;
    int d = ei[EE + e];
    atomicAdd(&easum[d * 18 + k], ea[i]);
    if (k == 0) atomicAdd(&deg[d], 1.0f);
}

// ---------------- generic row-tiled linear: y = [relu](x @ W + b) ----------------
__global__ void k_linear(const float* __restrict__ x, const float* __restrict__ W,
                         const float* __restrict__ b, float* __restrict__ y,
                         int nrows, int cin, int cout, int do_relu) {
    extern __shared__ float xs[];  // [4][cin]
    int base = blockIdx.x * 4;
    for (int idx = threadIdx.x; idx < 4 * cin; idx += blockDim.x) {
        int r = idx / cin, k = idx - r * cin;
        xs[idx] = (base + r < nrows) ? x[(base + r) * cin + k] : 0.f;
    }
    __syncthreads();
    for (int c = threadIdx.x; c < cout; c += blockDim.x) {
        float a0 = 0.f, a1 = 0.f, a2 = 0.f, a3 = 0.f;
        const float* x0 = xs;
        const float* x1 = xs + cin;
        const float* x2 = xs + 2 * cin;
        const float* x3 = xs + 3 * cin;
        for (int k = 0; k < cin; k++) {
            float wv = W[k * cout + c];
            a0 += x0[k] * wv; a1 += x1[k] * wv; a2 += x2[k] * wv; a3 += x3[k] * wv;
        }
        float bb = b[c];
        a0 += bb; a1 += bb; a2 += bb; a3 += bb;
        if (do_relu) {
            a0 = fmaxf(a0, 0.f); a1 = fmaxf(a1, 0.f);
            a2 = fmaxf(a2, 0.f); a3 = fmaxf(a3, 0.f);
        }
        if (base + 0 < nrows) y[(base + 0) * cout + c] = a0;
        if (base + 1 < nrows) y[(base + 1) * cout + c] = a1;
        if (base + 2 < nrows) y[(base + 2) * cout + c] = a2;
        if (base + 3 < nrows) y[(base + 3) * cout + c] = a3;
    }
}

// ---------------- GATv2 edge score: one warp per edge ----------------
// s_e = a . leaky_relu(xl[src] + xr[dst] + ea_e @ We, 0.2); atomicMax m[dst]
__global__ void k_score(const int* __restrict__ ei, const float* __restrict__ ea,
                        const float* __restrict__ easum, const float* __restrict__ deg,
                        const float* __restrict__ We, const float* __restrict__ av,
                        const float* __restrict__ xl, const float* __restrict__ xr,
                        float* __restrict__ s, unsigned* __restrict__ m, int C) {
    int e = (blockIdx.x * blockDim.x + threadIdx.x) >> 5;
    int lane = threadIdx.x & 31;
    if (e >= E2T) return;
    int sn, dn;
    float eav = 0.f;
    if (e < EE) {
        sn = ei[e]; dn = ei[EE + e];
        if (lane < 18) eav = ea[e * 18 + lane];
    } else {
        int n = e - EE; sn = n; dn = n;
        if (lane < 18) eav = easum[n * 18 + lane] / fmaxf(deg[n], 1.0f);
    }
    // Broadcast the 18 edge-attr values to ALL lanes while the warp is fully
    // converged (shuffles inside the strided c-loop were UB: trailing
    // iterations are lane-divergent for C % 32 != 0).
    float eaw[18];
#pragma unroll
    for (int k = 0; k < 18; k++) eaw[k] = __shfl_sync(0xffffffffu, eav, k);

    float acc = 0.f;
    for (int c = lane; c < C; c += 32) {
        float v = xl[sn * C + c] + xr[dn * C + c];
#pragma unroll
        for (int k = 0; k < 18; k++)
            v += eaw[k] * We[k * C + c];
        v = (v > 0.f) ? v : 0.2f * v;
        acc += av[c] * v;
    }
    for (int o = 16; o; o >>= 1) acc += __shfl_down_sync(0xffffffffu, acc, o);
    if (lane == 0) {
        s[e] = acc;
        atomicMax(&m[dn], fmap(acc));
    }
}

// ---------------- exp + denominator ----------------
__global__ void k_expz(const int* __restrict__ ei, float* __restrict__ s,
                       const unsigned* __restrict__ m, float* __restrict__ z) {
    int e = blockIdx.x * blockDim.x + threadIdx.x;
    if (e >= E2T) return;
    int dn = (e < EE) ? ei[EE + e] : (e - EE);
    float ex = expf(s[e] - funmap(m[dn]));
    s[e] = ex;
    atomicAdd(&z[dn], ex);
}

// ---------------- weighted aggregation: one warp per edge ----------------
__global__ void k_agg(const int* __restrict__ ei, const float* __restrict__ s,
                      const float* __restrict__ z, const float* __restrict__ xl,
                      float* __restrict__ out, int C) {
    int e = (blockIdx.x * blockDim.x + threadIdx.x) >> 5;
    int lane = threadIdx.x & 31;
    if (e >= E2T) return;
    int sn, dn;
    if (e < EE) { sn = ei[e]; dn = ei[EE + e]; }
    else        { sn = e - EE; dn = sn; }
    float alpha = s[e] / z[dn];
    for (int c = lane; c < C; c += 32)
        atomicAdd(&out[dn * C + c], alpha * xl[sn * C + c]);
}

// ---------------- bias + relu epilogue ----------------
__global__ void k_bias_relu(float* __restrict__ h, const float* __restrict__ b,
                            int total, int C) {
    int i = blockIdx.x * blockDim.x + threadIdx.x;
    if (i >= total) return;
    h[i] = fmaxf(h[i] + b[i % C], 0.f);
}

// ---------------- mean pooling ----------------
__global__ void k_pool(const float* __restrict__ h3, const int* __restrict__ bid,
                       float* __restrict__ pool, float* __restrict__ cnt) {
    int i = blockIdx.x * blockDim.x + threadIdx.x;
    if (i >= NN * 400) return;
    int n = i / 400, c = i - n * 400;
    int g = bid[n];
    atomicAdd(&pool[g * 400 + c], h3[i]);
    if (c == 0) atomicAdd(&cnt[g], 1.0f);
}

__global__ void k_pooldiv(float* __restrict__ pool, const float* __restrict__ cnt) {
    int i = blockIdx.x * blockDim.x + threadIdx.x;
    if (i >= GG * 400) return;
    pool[i] /= fmaxf(cnt[i / 400], 1.0f);
}

// ---------------- launch ----------------
extern "C" void kernel_launch(void* const* d_in, const int* in_sizes, int n_in,
                              void* d_out, int out_size) {
    const float* x   = (const float*)d_in[0];
    const int*   ei  = (const int*)d_in[1];
    const float* ea  = (const float*)d_in[2];
    const int*   bid = (const int*)d_in[3];
    const float* W1l = (const float*)d_in[4];
    const float* b1l = (const float*)d_in[5];
    const float* W1r = (const float*)d_in[6];
    const float* b1r = (const float*)d_in[7];
    const float* W1e = (const float*)d_in[8];
    const float* a1  = (const float*)d_in[9];
    const float* c1  = (const float*)d_in[10];
    const float* W2l = (const float*)d_in[11];
    const float* b2l = (const float*)d_in[12];
    const float* W2r = (const float*)d_in[13];
    const float* b2r = (const float*)d_in[14];
    const float* W2e = (const float*)d_in[15];
    const float* a2  = (const float*)d_in[16];
    const float* c2  = (const float*)d_in[17];
    const float* W3  = (const float*)d_in[18];
    const float* b3  = (const float*)d_in[19];
    const float* F1  = (const float*)d_in[20];
    const float* bf1 = (const float*)d_in[21];
    const float* F2  = (const float*)d_in[22];
    const float* bf2 = (const float*)d_in[23];
    const float* F3  = (const float*)d_in[24];
    const float* bf3 = (const float*)d_in[25];

    float *xl1, *xr1, *out1, *xl2, *xr2, *out2, *h3, *s, *z, *deg, *easum, *pool, *cnt, *y1, *y2;
    unsigned* m;
    cudaGetSymbolAddress((void**)&xl1,  g_xl1);
    cudaGetSymbolAddress((void**)&xr1,  g_xr1);
    cudaGetSymbolAddress((void**)&out1, g_out1);
    cudaGetSymbolAddress((void**)&xl2,  g_xl2);
    cudaGetSymbolAddress((void**)&xr2,  g_xr2);
    cudaGetSymbolAddress((void**)&out2, g_out2);
    cudaGetSymbolAddress((void**)&h3,   g_h3);
    cudaGetSymbolAddress((void**)&s,    g_s);
    cudaGetSymbolAddress((void**)&m,    g_m);
    cudaGetSymbolAddress((void**)&z,    g_z);
    cudaGetSymbolAddress((void**)&deg,  g_deg);
    cudaGetSymbolAddress((void**)&easum,g_easum);
    cudaGetSymbolAddress((void**)&pool, g_pool);
    cudaGetSymbolAddress((void**)&cnt,  g_cnt);
    cudaGetSymbolAddress((void**)&y1,   g_y1);
    cudaGetSymbolAddress((void**)&y2,   g_y2);

    const int T = 256;
    const int edgeWarpGrid = (E2T + 7) / 8;  // 8 warps (256 threads) per block

    // --- self-loop attrs ---
    cudaMemsetAsync(deg, 0, NN * sizeof(float));
    cudaMemsetAsync(easum, 0, NN * 18 * sizeof(float));
    k_ea_accum<<<(EE * 18 + T - 1) / T, T>>>(ei, ea, deg, easum);

    // --- layer 1 (Cin=16 -> C=100) ---
    k_linear<<<(NN + 3) / 4, T, 4 * 16 * sizeof(float)>>>(x, W1l, b1l, xl1, NN, 16, 100, 0);
    k_linear<<<(NN + 3) / 4, T, 4 * 16 * sizeof(float)>>>(x, W1r, b1r, xr1, NN, 16, 100, 0);
    cudaMemsetAsync(m, 0, NN * sizeof(unsigned));
    cudaMemsetAsync(z, 0, NN * sizeof(float));
    k_score<<<edgeWarpGrid, T>>>(ei, ea, easum, deg, W1e, a1, xl1, xr1, s, m, 100);
    k_expz<<<(E2T + T - 1) / T, T>>>(ei, s, m, z);
    cudaMemsetAsync(out1, 0, (size_t)NN * 100 * sizeof(float));
    k_agg<<<edgeWarpGrid, T>>>(ei, s, z, xl1, out1, 100);
    k_bias_relu<<<(NN * 100 + T - 1) / T, T>>>(out1, c1, NN * 100, 100);

    // --- layer 2 (Cin=100 -> C=200) ---
    k_linear<<<(NN + 3) / 4, T, 4 * 100 * sizeof(float)>>>(out1, W2l, b2l, xl2, NN, 100, 200, 0);
    k_linear<<<(NN + 3) / 4, T, 4 * 100 * sizeof(float)>>>(out1, W2r, b2r, xr2, NN, 100, 200, 0);
    cudaMemsetAsync(m, 0, NN * sizeof(unsigned));
    cudaMemsetAsync(z, 0, NN * sizeof(float));
    k_score<<<edgeWarpGrid, T>>>(ei, ea, easum, deg, W2e, a2, xl2, xr2, s, m, 200);
    k_expz<<<(E2T + T - 1) / T, T>>>(ei, s, m, z);
    cudaMemsetAsync(out2, 0, (size_t)NN * 200 * sizeof(float));
    k_agg<<<edgeWarpGrid, T>>>(ei, s, z, xl2, out2, 200);
    k_bias_relu<<<(NN * 200 + T - 1) / T, T>>>(out2, c2, NN * 200, 200);

    // --- h3 = h2 @ W3 + b3 ---
    k_linear<<<(NN + 3) / 4, T, 4 * 200 * sizeof(float)>>>(out2, W3, b3, h3, NN, 200, 400, 0);

    // --- mean pool over graphs ---
    cudaMemsetAsync(pool, 0, GG * 400 * sizeof(float));
    cudaMemsetAsync(cnt, 0, GG * sizeof(float));
    k_pool<<<(NN * 400 + T - 1) / T, T>>>(h3, bid, pool, cnt);
    k_pooldiv<<<(GG * 400 + T - 1) / T, T>>>(pool, cnt);

    // --- FFN head ---
    k_linear<<<(GG + 3) / 4, T, 4 * 400 * sizeof(float)>>>(pool, F1, bf1, y1, GG, 400, 200, 1);
    k_linear<<<(GG + 3) / 4, T, 4 * 200 * sizeof(float)>>>(y1, F2, bf2, y2, GG, 200, 100, 1);
    k_linear<<<(GG + 3) / 4, T, 4 * 100 * sizeof(float)>>>(y2, F3, bf3, (float*)d_out, GG, 100, 100, 0);
}

// round 5
// speedup vs baseline: 1.2258x; 1.2258x over previous
#include <cuda_runtime.h>
#include <math.h>

#define NN 50000
#define EE 1600000
#define E2T (EE + NN)
#define GG 512

// ---------------- scratch (allocation-free: __device__ globals) ----------------
__device__ float g_xl1[NN * 100];
__device__ float g_xr1[NN * 100];
__device__ float g_out1[NN * 100];
__device__ float g_xl2[NN * 200];
__device__ float g_xr2[NN * 200];
__device__ float g_out2[NN * 200];
__device__ float g_h3[NN * 400];
__device__ float g_s[E2T];      // edge scores, CSR-ordered
__device__ float g_w[E2T];      // exp weights, CSR-ordered
__device__ float g_loop[NN * 18]; // self-loop edge attrs (mean of incoming)
__device__ int   g_cnt[NN];     // CSR histogram
__device__ int   g_off[NN + 1]; // CSR row offsets
__device__ int   g_cur[NN];     // scatter cursors
__device__ int   g_ce[E2T];     // CSR pos -> edge id
__device__ int   g_csrc[E2T];   // CSR pos -> src node
__device__ int   g_pos[E2T];    // edge id -> CSR pos
__device__ float g_pool[GG * 400];
__device__ float g_gcnt[GG];
__device__ float g_y1[GG * 200];
__device__ float g_y2[GG * 100];

// ---------------- CSR build ----------------
__global__ void k_hist(const int* __restrict__ ei, int* __restrict__ cnt) {
    int i = blockIdx.x * blockDim.x + threadIdx.x;
    if (i < EE) {
        atomicAdd(&cnt[ei[EE + i]], 1);
    } else if (i < EE + NN) {
        atomicAdd(&cnt[i - EE], 1);   // self loop
    }
}

__global__ void k_scan(const int* __restrict__ cnt, int* __restrict__ off) {
    __shared__ int ssum[1024];
    int t = threadIdx.x;
    const int NPT = (NN + 1023) / 1024;
    int base = t * NPT;
    int local = 0;
    for (int i = 0; i < NPT; i++)
        if (base + i < NN) local += cnt[base + i];
    ssum[t] = local;
    __syncthreads();
    for (int o = 1; o < 1024; o <<= 1) {
        int v = (t >= o) ? ssum[t - o] : 0;
        __syncthreads();
        ssum[t] += v;
        __syncthreads();
    }
    int run = ssum[t] - local;  // exclusive prefix
    for (int i = 0; i < NPT; i++) {
        int idx = base + i;
        if (idx < NN) { off[idx] = run; run += cnt[idx]; }
    }
    if (t == 1023) off[NN] = run;
}

__global__ void k_scatter(const int* __restrict__ ei, const int* __restrict__ off,
                          int* __restrict__ cur, int* __restrict__ ce,
                          int* __restrict__ csrc, int* __restrict__ pos) {
    int e = blockIdx.x * blockDim.x + threadIdx.x;
    if (e >= E2T) return;
    int sn, dn;
    if (e < EE) { sn = ei[e]; dn = ei[EE + e]; }
    else        { sn = e - EE; dn = sn; }
    int p = off[dn] + atomicAdd(&cur[dn], 1);
    ce[p] = e;
    csrc[p] = sn;
    pos[e] = p;
}

// ---------------- self-loop attr = mean of incoming edge attrs ----------------
// one warp per node, lanes 0..17 own the 18 channels
__global__ void k_loopattr(const int* __restrict__ off, const int* __restrict__ ce,
                           const float* __restrict__ ea, float* __restrict__ loop) {
    int n = (blockIdx.x * blockDim.x + threadIdx.x) >> 5;
    int lane = threadIdx.x & 31;
    if (n >= NN) return;
    int start = off[n], end = off[n + 1];
    float acc = 0.f;
    for (int i = start; i < end; i++) {
        int e = ce[i];             // broadcast load
        if (e < EE && lane < 18) acc += ea[e * 18 + lane];
    }
    float deg = (float)(end - start - 1);   // excl. self loop
    if (lane < 18) loop[n * 18 + lane] = acc / fmaxf(deg, 1.0f);
}

// ---------------- row-tiled linear: y = [relu](x @ W + b), 8 rows/block ----------------
__global__ void k_linear(const float* __restrict__ x, const float* __restrict__ W,
                         const float* __restrict__ b, float* __restrict__ y,
                         int nrows, int cin, int cout, int do_relu) {
    extern __shared__ float xs[];  // [8][cin]
    int base = blockIdx.x * 8;
    for (int idx = threadIdx.x; idx < 8 * cin; idx += blockDim.x) {
        int r = idx / cin, k = idx - r * cin;
        xs[idx] = (base + r < nrows) ? x[(base + r) * cin + k] : 0.f;
    }
    __syncthreads();
    for (int c = threadIdx.x; c < cout; c += blockDim.x) {
        float a0 = 0.f, a1 = 0.f, a2 = 0.f, a3 = 0.f;
        float a4 = 0.f, a5 = 0.f, a6 = 0.f, a7 = 0.f;
        for (int k = 0; k < cin; k++) {
            float wv = W[k * cout + c];
            a0 += xs[k] * wv;            a1 += xs[cin + k] * wv;
            a2 += xs[2 * cin + k] * wv;  a3 += xs[3 * cin + k] * wv;
            a4 += xs[4 * cin + k] * wv;  a5 += xs[5 * cin + k] * wv;
            a6 += xs[6 * cin + k] * wv;  a7 += xs[7 * cin + k] * wv;
        }
        float bb = b[c];
        float v[8] = {a0 + bb, a1 + bb, a2 + bb, a3 + bb,
                      a4 + bb, a5 + bb, a6 + bb, a7 + bb};
#pragma unroll
        for (int r = 0; r < 8; r++) {
            float o = do_relu ? fmaxf(v[r], 0.f) : v[r];
            if (base + r < nrows) y[(base + r) * cout + c] = o;
        }
    }
}

// ---------------- GATv2 edge score: one warp per edge, We+a in smem ----------------
template <int C>
__global__ void k_score(const int* __restrict__ ei, const float* __restrict__ ea,
                        const float* __restrict__ loop, const float* __restrict__ We,
                        const float* __restrict__ av, const float* __restrict__ xl,
                        const float* __restrict__ xr, const int* __restrict__ pos,
                        float* __restrict__ s) {
    extern __shared__ float sm[];   // [18*C We][C a]
    float* sWe = sm;
    float* sa = sm + 18 * C;
    for (int i = threadIdx.x; i < 18 * C; i += blockDim.x) sWe[i] = We[i];
    for (int i = threadIdx.x; i < C; i += blockDim.x) sa[i] = av[i];
    __syncthreads();

    int e = (blockIdx.x * blockDim.x + threadIdx.x) >> 5;
    int lane = threadIdx.x & 31;
    if (e >= E2T) return;
    int sn, dn;
    float eav = 0.f;
    if (e < EE) {
        sn = ei[e]; dn = ei[EE + e];
        if (lane < 18) eav = ea[e * 18 + lane];
    } else {
        int n = e - EE; sn = n; dn = n;
        if (lane < 18) eav = loop[n * 18 + lane];
    }
    // broadcast edge attrs while warp fully converged
    float eaw[18];
#pragma unroll
    for (int k = 0; k < 18; k++) eaw[k] = __shfl_sync(0xffffffffu, eav, k);

    float acc = 0.f;
    for (int c = lane; c < C; c += 32) {
        float v = xl[sn * C + c] + xr[dn * C + c];
#pragma unroll
        for (int k = 0; k < 18; k++)
            v += eaw[k] * sWe[k * C + c];
        v = (v > 0.f) ? v : 0.2f * v;
        acc += sa[c] * v;
    }
#pragma unroll
    for (int o = 16; o; o >>= 1) acc += __shfl_down_sync(0xffffffffu, acc, o);
    if (lane == 0) s[pos[e]] = acc;   // CSR-ordered
}

// ---------------- fused softmax + aggregation + bias + relu: warp per node ----------------
template <int C>
__global__ void k_softmax_agg(const int* __restrict__ off, const int* __restrict__ csrc,
                              const float* __restrict__ s, float* __restrict__ w,
                              const float* __restrict__ xl, const float* __restrict__ bias,
                              float* __restrict__ out) {
    int n = (blockIdx.x * blockDim.x + threadIdx.x) >> 5;
    int lane = threadIdx.x & 31;
    if (n >= NN) return;
    int start = off[n], end = off[n + 1];

    // pass 1: max (coalesced CSR reads)
    float m = -3.0e38f;
    for (int i = start + lane; i < end; i += 32) m = fmaxf(m, s[i]);
#pragma unroll
    for (int o = 16; o; o >>= 1) m = fmaxf(m, __shfl_xor_sync(0xffffffffu, m, o));

    // pass 2: exp + denominator
    float z = 0.f;
    for (int i = start + lane; i < end; i += 32) {
        float wv = __expf(s[i] - m);
        w[i] = wv;
        z += wv;
    }
#pragma unroll
    for (int o = 16; o; o >>= 1) z += __shfl_xor_sync(0xffffffffu, z, o);
    float invz = __fdividef(1.0f, z);

    // pass 3: weighted aggregation over edges (serial edges, parallel channels)
    constexpr int NC = (C + 31) / 32;
    float acc[NC];
#pragma unroll
    for (int j = 0; j < NC; j++) acc[j] = 0.f;
    for (int i = start; i < end; i++) {
        float wv = w[i];            // broadcast load
        int sn = csrc[i];           // broadcast load
        const float* xp = xl + (size_t)sn * C;
#pragma unroll
        for (int j = 0; j < NC; j++) {
            int c = lane + 32 * j;
            if (c < C) acc[j] += wv * xp[c];
        }
    }
#pragma unroll
    for (int j = 0; j < NC; j++) {
        int c = lane + 32 * j;
        if (c < C) out[(size_t)n * C + c] = fmaxf(acc[j] * invz + bias[c], 0.f);
    }
}

// ---------------- h3 has no relu: variant writing without relu is k_linear(do_relu=0) ----

// ---------------- mean pooling ----------------
__global__ void k_pool(const float* __restrict__ h3, const int* __restrict__ bid,
                       float* __restrict__ pool, float* __restrict__ cnt) {
    int i = blockIdx.x * blockDim.x + threadIdx.x;
    if (i >= NN * 400) return;
    int n = i / 400, c = i - n * 400;
    int g = bid[n];
    atomicAdd(&pool[g * 400 + c], h3[i]);
    if (c == 0) atomicAdd(&cnt[g], 1.0f);
}

__global__ void k_pooldiv(float* __restrict__ pool, const float* __restrict__ cnt) {
    int i = blockIdx.x * blockDim.x + threadIdx.x;
    if (i >= GG * 400) return;
    pool[i] /= fmaxf(cnt[i / 400], 1.0f);
}

// ---------------- launch ----------------
extern "C" void kernel_launch(void* const* d_in, const int* in_sizes, int n_in,
                              void* d_out, int out_size) {
    const float* x   = (const float*)d_in[0];
    const int*   ei  = (const int*)d_in[1];
    const float* ea  = (const float*)d_in[2];
    const int*   bid = (const int*)d_in[3];
    const float* W1l = (const float*)d_in[4];
    const float* b1l = (const float*)d_in[5];
    const float* W1r = (const float*)d_in[6];
    const float* b1r = (const float*)d_in[7];
    const float* W1e = (const float*)d_in[8];
    const float* a1  = (const float*)d_in[9];
    const float* c1  = (const float*)d_in[10];
    const float* W2l = (const float*)d_in[11];
    const float* b2l = (const float*)d_in[12];
    const float* W2r = (const float*)d_in[13];
    const float* b2r = (const float*)d_in[14];
    const float* W2e = (const float*)d_in[15];
    const float* a2  = (const float*)d_in[16];
    const float* c2  = (const float*)d_in[17];
    const float* W3  = (const float*)d_in[18];
    const float* b3  = (const float*)d_in[19];
    const float* F1  = (const float*)d_in[20];
    const float* bf1 = (const float*)d_in[21];
    const float* F2  = (const float*)d_in[22];
    const float* bf2 = (const float*)d_in[23];
    const float* F3  = (const float*)d_in[24];
    const float* bf3 = (const float*)d_in[25];

    float *xl1, *xr1, *out1, *xl2, *xr2, *out2, *h3, *s, *w, *loop, *pool, *gcnt, *y1, *y2;
    int *cnt, *off, *cur, *ce, *csrc, *pos;
    cudaGetSymbolAddress((void**)&xl1,  g_xl1);
    cudaGetSymbolAddress((void**)&xr1,  g_xr1);
    cudaGetSymbolAddress((void**)&out1, g_out1);
    cudaGetSymbolAddress((void**)&xl2,  g_xl2);
    cudaGetSymbolAddress((void**)&xr2,  g_xr2);
    cudaGetSymbolAddress((void**)&out2, g_out2);
    cudaGetSymbolAddress((void**)&h3,   g_h3);
    cudaGetSymbolAddress((void**)&s,    g_s);
    cudaGetSymbolAddress((void**)&w,    g_w);
    cudaGetSymbolAddress((void**)&loop, g_loop);
    cudaGetSymbolAddress((void**)&cnt,  g_cnt);
    cudaGetSymbolAddress((void**)&off,  g_off);
    cudaGetSymbolAddress((void**)&cur,  g_cur);
    cudaGetSymbolAddress((void**)&ce,   g_ce);
    cudaGetSymbolAddress((void**)&csrc, g_csrc);
    cudaGetSymbolAddress((void**)&pos,  g_pos);
    cudaGetSymbolAddress((void**)&pool, g_pool);
    cudaGetSymbolAddress((void**)&gcnt, g_gcnt);
    cudaGetSymbolAddress((void**)&y1,   g_y1);
    cudaGetSymbolAddress((void**)&y2,   g_y2);

    const int T = 256;
    const int edgeWarpGrid = (E2T + 7) / 8;    // warp per edge, 8 warps/block
    const int nodeWarpGrid = (NN + 7) / 8;     // warp per node

    // --- CSR by dst (includes self-loops) ---
    cudaMemsetAsync(cnt, 0, NN * sizeof(int));
    cudaMemsetAsync(cur, 0, NN * sizeof(int));
    k_hist<<<(EE + NN + T - 1) / T, T>>>(ei, cnt);
    k_scan<<<1, 1024>>>(cnt, off);
    k_scatter<<<(E2T + T - 1) / T, T>>>(ei, off, cur, ce, csrc, pos);
    k_loopattr<<<nodeWarpGrid, T>>>(off, ce, ea, loop);

    // --- layer 1 (16 -> 100) ---
    k_linear<<<(NN + 7) / 8, T, 8 * 16 * sizeof(float)>>>(x, W1l, b1l, xl1, NN, 16, 100, 0);
    k_linear<<<(NN + 7) / 8, T, 8 * 16 * sizeof(float)>>>(x, W1r, b1r, xr1, NN, 16, 100, 0);
    k_score<100><<<edgeWarpGrid, T, 19 * 100 * sizeof(float)>>>(ei, ea, loop, W1e, a1, xl1, xr1, pos, s);
    k_softmax_agg<100><<<nodeWarpGrid, T>>>(off, csrc, s, w, xl1, c1, out1);

    // --- layer 2 (100 -> 200) ---
    k_linear<<<(NN + 7) / 8, T, 8 * 100 * sizeof(float)>>>(out1, W2l, b2l, xl2, NN, 100, 200, 0);
    k_linear<<<(NN + 7) / 8, T, 8 * 100 * sizeof(float)>>>(out1, W2r, b2r, xr2, NN, 100, 200, 0);
    k_score<200><<<edgeWarpGrid, T, 19 * 200 * sizeof(float)>>>(ei, ea, loop, W2e, a2, xl2, xr2, pos, s);
    k_softmax_agg<200><<<nodeWarpGrid, T>>>(off, csrc, s, w, xl2, c2, out2);

    // --- h3 = h2 @ W3 + b3 ---
    k_linear<<<(NN + 7) / 8, T, 8 * 200 * sizeof(float)>>>(out2, W3, b3, h3, NN, 200, 400, 0);

    // --- mean pool over graphs ---
    cudaMemsetAsync(pool, 0, GG * 400 * sizeof(float));
    cudaMemsetAsync(gcnt, 0, GG * sizeof(float));
    k_pool<<<(NN * 400 + T - 1) / T, T>>>(h3, bid, pool, gcnt);
    k_pooldiv<<<(GG * 400 + T - 1) / T, T>>>(pool, gcnt);

    // --- FFN head ---
    k_linear<<<(GG + 7) / 8, T, 8 * 400 * sizeof(float)>>>(pool, F1, bf1, y1, GG, 400, 200, 1);
    k_linear<<<(GG + 7) / 8, T, 8 * 200 * sizeof(float)>>>(y1, F2, bf2, y2, GG, 200, 100, 1);
    k_linear<<<(GG + 7) / 8, T, 8 * 100 * sizeof(float)>>>(y2, F3, bf3, (float*)d_out, GG, 100, 100, 0);
}

// round 6
// speedup vs baseline: 2.2730x; 1.8542x over previous
#include <cuda_runtime.h>
#include <math.h>

#define NN 50000
#define EE 1600000
#define E2T (EE + NN)
#define GG 512
#define NEG 0.2f

// ---------------- scratch (allocation-free: __device__ globals) ----------------
__device__ float g_xl1[NN * 100];
__device__ float g_xr1[NN * 100];
__device__ float g_out1[NN * 100];
__device__ float g_xl2[NN * 200];
__device__ float g_xr2[NN * 200];
__device__ float g_out2[NN * 200];
__device__ float g_eac[(size_t)E2T * 18];  // edge attrs, CSR-ordered (incl. self-loop means)
__device__ int   g_cnt[NN];
__device__ int   g_off[NN + 1];
__device__ int   g_cur[NN];
__device__ int   g_csrc[E2T];   // CSR pos -> src node
__device__ int   g_pos[E2T];    // edge id -> CSR pos
__device__ float g_pool2[GG * 200];
__device__ float g_gcnt[GG];
__device__ float g_pool3[GG * 400];
__device__ float g_y1[GG * 200];
__device__ float g_y2[GG * 100];

// ---------------- CSR build ----------------
__global__ void k_hist(const int* __restrict__ ei, int* __restrict__ cnt) {
    int i = blockIdx.x * blockDim.x + threadIdx.x;
    if (i < EE) atomicAdd(&cnt[ei[EE + i]], 1);
    else if (i < EE + NN) atomicAdd(&cnt[i - EE], 1);   // self loop
}

__global__ void k_scan(const int* __restrict__ cnt, int* __restrict__ off) {
    __shared__ int ssum[1024];
    int t = threadIdx.x;
    const int NPT = (NN + 1023) / 1024;
    int base = t * NPT;
    int local = 0;
    for (int i = 0; i < NPT; i++)
        if (base + i < NN) local += cnt[base + i];
    ssum[t] = local;
    __syncthreads();
    for (int o = 1; o < 1024; o <<= 1) {
        int v = (t >= o) ? ssum[t - o] : 0;
        __syncthreads();
        ssum[t] += v;
        __syncthreads();
    }
    int run = ssum[t] - local;
    for (int i = 0; i < NPT; i++) {
        int idx = base + i;
        if (idx < NN) { off[idx] = run; run += cnt[idx]; }
    }
    if (t == 1023) off[NN] = run;
}

__global__ void k_scatter(const int* __restrict__ ei, const int* __restrict__ off,
                          int* __restrict__ cur, int* __restrict__ csrc,
                          int* __restrict__ pos) {
    int e = blockIdx.x * blockDim.x + threadIdx.x;
    if (e >= E2T) return;
    int sn, dn;
    if (e < EE) { sn = ei[e]; dn = ei[EE + e]; }
    else        { sn = e - EE; dn = sn; }
    int p = off[dn] + atomicAdd(&cur[dn], 1);
    csrc[p] = sn;
    pos[e] = p;
}

// gather edge attrs into CSR order
__global__ void k_eagather(const float* __restrict__ ea, const int* __restrict__ pos,
                           float* __restrict__ eac) {
    int i = blockIdx.x * blockDim.x + threadIdx.x;
    if (i >= EE * 18) return;
    int e = i / 18, k = i - e * 18;
    eac[(size_t)pos[e] * 18 + k] = ea[i];
}

// self-loop attr = mean of incoming real edge attrs; written in place into eac
__global__ void k_loopattr(const int* __restrict__ off, const int* __restrict__ pos,
                           float* __restrict__ eac) {
    int n = (blockIdx.x * blockDim.x + threadIdx.x) >> 5;
    int lane = threadIdx.x & 31;
    if (n >= NN) return;
    int start = off[n], end = off[n + 1];
    int selfpos = pos[EE + n];
    float acc = 0.f;
    if (lane < 18)
        for (int i = start; i < end; i++)
            if (i != selfpos) acc += eac[(size_t)i * 18 + lane];
    float deg = (float)(end - start - 1);
    if (lane < 18) eac[(size_t)selfpos * 18 + lane] = acc / fmaxf(deg, 1.0f);
}

// ---------------- register-tiled GEMM: C = [relu](A @ B + bias) ----------------
// A[M,K] row-major, B[K,N] row-major. 64x64 block tile, 4x4 per thread, BK=16.
__global__ void k_gemm(const float* __restrict__ A, const float* __restrict__ B,
                       const float* __restrict__ bias, float* __restrict__ Cm,
                       int M, int K, int N, int relu) {
    __shared__ float As[16][64];  // [k][m]
    __shared__ float Bs[16][64];  // [k][n]
    int bm = blockIdx.y * 64, bn = blockIdx.x * 64;
    int tid = threadIdx.x;
    int tx = tid & 15, ty = tid >> 4;
    float acc[4][4];
#pragma unroll
    for (int r = 0; r < 4; r++)
#pragma unroll
        for (int c = 0; c < 4; c++) acc[r][c] = 0.f;

    for (int k0 = 0; k0 < K; k0 += 16) {
        for (int l = tid; l < 64 * 16; l += 256) {
            int r = l >> 4, kk = l & 15;
            As[kk][r] = (bm + r < M && k0 + kk < K) ? A[(size_t)(bm + r) * K + k0 + kk] : 0.f;
        }
        for (int l = tid; l < 16 * 64; l += 256) {
            int kk = l >> 6, c = l & 63;
            Bs[kk][c] = (k0 + kk < K && bn + c < N) ? B[(size_t)(k0 + kk) * N + bn + c] : 0.f;
        }
        __syncthreads();
#pragma unroll
        for (int kk = 0; kk < 16; kk++) {
            float av[4], bv[4];
#pragma unroll
            for (int r = 0; r < 4; r++) av[r] = As[kk][ty * 4 + r];
#pragma unroll
            for (int c = 0; c < 4; c++) bv[c] = Bs[kk][tx * 4 + c];
#pragma unroll
            for (int r = 0; r < 4; r++)
#pragma unroll
                for (int c = 0; c < 4; c++) acc[r][c] += av[r] * bv[c];
        }
        __syncthreads();
    }
#pragma unroll
    for (int r = 0; r < 4; r++) {
        int row = bm + ty * 4 + r;
        if (row >= M) continue;
#pragma unroll
        for (int c = 0; c < 4; c++) {
            int col = bn + tx * 4 + c;
            if (col < N) {
                float v = acc[r][c] + bias[col];
                Cm[(size_t)row * N + col] = relu ? fmaxf(v, 0.f) : v;
            }
        }
    }
}

// ---------------- fused GATv2: score + online softmax + aggregate + bias + relu ----
// one warp per node; 2 edges per iteration to halve sWe smem traffic
template <int C, int NC>
__global__ __launch_bounds__(128)
void k_gat(const int* __restrict__ off, const int* __restrict__ csrc,
           const float* __restrict__ eac, const float* __restrict__ We,
           const float* __restrict__ av, const float* __restrict__ xl,
           const float* __restrict__ xr, const float* __restrict__ bias,
           float* __restrict__ out) {
    extern __shared__ float sWe[];  // [18][C]
    for (int idx = threadIdx.x; idx < 18 * C; idx += blockDim.x) sWe[idx] = We[idx];
    __syncthreads();

    int n = (blockIdx.x * blockDim.x + threadIdx.x) >> 5;
    int lane = threadIdx.x & 31;
    if (n >= NN) return;

    float avr[NC], xrr[NC], acc[NC];
#pragma unroll
    for (int j = 0; j < NC; j++) {
        int c = lane + 32 * j;
        avr[j] = (c < C) ? av[c] : 0.f;
        xrr[j] = (c < C) ? xr[(size_t)n * C + c] : 0.f;
        acc[j] = 0.f;
    }
    float m = -3.0e38f, z = 0.f;
    int start = off[n], end = off[n + 1];
    int i = start;

    for (; i + 1 < end; i += 2) {
        int s0 = csrc[i], s1 = csrc[i + 1];
        float a0v = 0.f, a1v = 0.f;
        if (lane < 18) {
            a0v = eac[(size_t)i * 18 + lane];
            a1v = eac[(size_t)i * 18 + 18 + lane];
        }
        float e0[18], e1[18];
#pragma unroll
        for (int k = 0; k < 18; k++) {
            e0[k] = __shfl_sync(0xffffffffu, a0v, k);
            e1[k] = __shfl_sync(0xffffffffu, a1v, k);
        }
        const float* p0 = xl + (size_t)s0 * C;
        const float* p1 = xl + (size_t)s1 * C;
        float x0[NC], x1[NC], v0[NC], v1[NC];
#pragma unroll
        for (int j = 0; j < NC; j++) {
            int c = lane + 32 * j;
            x0[j] = (c < C) ? p0[c] : 0.f;
            x1[j] = (c < C) ? p1[c] : 0.f;
            v0[j] = x0[j] + xrr[j];
            v1[j] = x1[j] + xrr[j];
        }
#pragma unroll
        for (int k = 0; k < 18; k++) {
#pragma unroll
            for (int j = 0; j < NC; j++) {
                int c = lane + 32 * j;
                float w_ = (c < C) ? sWe[k * C + c] : 0.f;
                v0[j] += e0[k] * w_;
                v1[j] += e1[k] * w_;
            }
        }
        float sc0 = 0.f, sc1 = 0.f;
#pragma unroll
        for (int j = 0; j < NC; j++) {
            float t0 = v0[j]; sc0 += avr[j] * ((t0 > 0.f) ? t0 : NEG * t0);
            float t1 = v1[j]; sc1 += avr[j] * ((t1 > 0.f) ? t1 : NEG * t1);
        }
#pragma unroll
        for (int o = 16; o; o >>= 1) {
            sc0 += __shfl_xor_sync(0xffffffffu, sc0, o);
            sc1 += __shfl_xor_sync(0xffffffffu, sc1, o);
        }
        float newm = fmaxf(m, fmaxf(sc0, sc1));
        float scale = __expf(m - newm);
        float w0 = __expf(sc0 - newm);
        float w1 = __expf(sc1 - newm);
        z = z * scale + w0 + w1;
#pragma unroll
        for (int j = 0; j < NC; j++)
            acc[j] = acc[j] * scale + w0 * x0[j] + w1 * x1[j];
        m = newm;
    }
    if (i < end) {  // odd tail edge
        int s0 = csrc[i];
        float a0v = 0.f;
        if (lane < 18) a0v = eac[(size_t)i * 18 + lane];
        float e0[18];
#pragma unroll
        for (int k = 0; k < 18; k++) e0[k] = __shfl_sync(0xffffffffu, a0v, k);
        const float* p0 = xl + (size_t)s0 * C;
        float x0[NC], v0[NC];
#pragma unroll
        for (int j = 0; j < NC; j++) {
            int c = lane + 32 * j;
            x0[j] = (c < C) ? p0[c] : 0.f;
            v0[j] = x0[j] + xrr[j];
        }
#pragma unroll
        for (int k = 0; k < 18; k++) {
#pragma unroll
            for (int j = 0; j < NC; j++) {
                int c = lane + 32 * j;
                float w_ = (c < C) ? sWe[k * C + c] : 0.f;
                v0[j] += e0[k] * w_;
            }
        }
        float sc0 = 0.f;
#pragma unroll
        for (int j = 0; j < NC; j++) {
            float t0 = v0[j]; sc0 += avr[j] * ((t0 > 0.f) ? t0 : NEG * t0);
        }
#pragma unroll
        for (int o = 16; o; o >>= 1) sc0 += __shfl_xor_sync(0xffffffffu, sc0, o);
        float newm = fmaxf(m, sc0);
        float scale = __expf(m - newm);
        float w0 = __expf(sc0 - newm);
        z = z * scale + w0;
#pragma unroll
        for (int j = 0; j < NC; j++) acc[j] = acc[j] * scale + w0 * x0[j];
    }
    float invz = __fdividef(1.0f, z);
#pragma unroll
    for (int j = 0; j < NC; j++) {
        int c = lane + 32 * j;
        if (c < C) out[(size_t)n * C + c] = fmaxf(acc[j] * invz + bias[c], 0.f);
    }
}

// ---------------- mean pooling of h2 (pool BEFORE the 200->400 linear) ----------------
__global__ void k_pool(const float* __restrict__ h, const int* __restrict__ bid,
                       float* __restrict__ pool, float* __restrict__ cnt) {
    int i = blockIdx.x * blockDim.x + threadIdx.x;
    if (i >= NN * 200) return;
    int n = i / 200, c = i - n * 200;
    int g = bid[n];
    atomicAdd(&pool[g * 200 + c], h[i]);
    if (c == 0) atomicAdd(&cnt[g], 1.0f);
}

__global__ void k_pooldiv(float* __restrict__ pool, const float* __restrict__ cnt) {
    int i = blockIdx.x * blockDim.x + threadIdx.x;
    if (i >= GG * 200) return;
    pool[i] /= fmaxf(cnt[i / 200], 1.0f);
}

// ---------------- launch ----------------
extern "C" void kernel_launch(void* const* d_in, const int* in_sizes, int n_in,
                              void* d_out, int out_size) {
    const float* x   = (const float*)d_in[0];
    const int*   ei  = (const int*)d_in[1];
    const float* ea  = (const float*)d_in[2];
    const int*   bid = (const int*)d_in[3];
    const float* W1l = (const float*)d_in[4];
    const float* b1l = (const float*)d_in[5];
    const float* W1r = (const float*)d_in[6];
    const float* b1r = (const float*)d_in[7];
    const float* W1e = (const float*)d_in[8];
    const float* a1  = (const float*)d_in[9];
    const float* c1  = (const float*)d_in[10];
    const float* W2l = (const float*)d_in[11];
    const float* b2l = (const float*)d_in[12];
    const float* W2r = (const float*)d_in[13];
    const float* b2r = (const float*)d_in[14];
    const float* W2e = (const float*)d_in[15];
    const float* a2  = (const float*)d_in[16];
    const float* c2  = (const float*)d_in[17];
    const float* W3  = (const float*)d_in[18];
    const float* b3  = (const float*)d_in[19];
    const float* F1  = (const float*)d_in[20];
    const float* bf1 = (const float*)d_in[21];
    const float* F2  = (const float*)d_in[22];
    const float* bf2 = (const float*)d_in[23];
    const float* F3  = (const float*)d_in[24];
    const float* bf3 = (const float*)d_in[25];

    float *xl1, *xr1, *out1, *xl2, *xr2, *out2, *eac, *pool2, *gcnt, *pool3, *y1, *y2;
    int *cnt, *off, *cur, *csrc, *pos;
    cudaGetSymbolAddress((void**)&xl1,   g_xl1);
    cudaGetSymbolAddress((void**)&xr1,   g_xr1);
    cudaGetSymbolAddress((void**)&out1,  g_out1);
    cudaGetSymbolAddress((void**)&xl2,   g_xl2);
    cudaGetSymbolAddress((void**)&xr2,   g_xr2);
    cudaGetSymbolAddress((void**)&out2,  g_out2);
    cudaGetSymbolAddress((void**)&eac,   g_eac);
    cudaGetSymbolAddress((void**)&cnt,   g_cnt);
    cudaGetSymbolAddress((void**)&off,   g_off);
    cudaGetSymbolAddress((void**)&cur,   g_cur);
    cudaGetSymbolAddress((void**)&csrc,  g_csrc);
    cudaGetSymbolAddress((void**)&pos,   g_pos);
    cudaGetSymbolAddress((void**)&pool2, g_pool2);
    cudaGetSymbolAddress((void**)&gcnt,  g_gcnt);
    cudaGetSymbolAddress((void**)&pool3, g_pool3);
    cudaGetSymbolAddress((void**)&y1,    g_y1);
    cudaGetSymbolAddress((void**)&y2,    g_y2);

    const int T = 256;
    const int gatGrid = (NN + 3) / 4;        // warp per node, 4 warps (128 thr) / block
    const int nodeWarpGrid = (NN + 7) / 8;   // warp per node, 256 thr / block

    // --- CSR by dst (incl. self-loops) + CSR-ordered edge attrs ---
    cudaMemsetAsync(cnt, 0, NN * sizeof(int));
    cudaMemsetAsync(cur, 0, NN * sizeof(int));
    k_hist<<<(EE + NN + T - 1) / T, T>>>(ei, cnt);
    k_scan<<<1, 1024>>>(cnt, off);
    k_scatter<<<(E2T + T - 1) / T, T>>>(ei, off, cur, csrc, pos);
    k_eagather<<<(EE * 18 + T - 1) / T, T>>>(ea, pos, eac);
    k_loopattr<<<nodeWarpGrid, T>>>(off, pos, eac);

    // --- layer 1: xl1/xr1 = x@W + b (16 -> 100), then fused GAT ---
    {
        dim3 g((100 + 63) / 64, (NN + 63) / 64);
        k_gemm<<<g, 256>>>(x, W1l, b1l, xl1, NN, 16, 100, 0);
        k_gemm<<<g, 256>>>(x, W1r, b1r, xr1, NN, 16, 100, 0);
    }
    k_gat<100, 4><<<gatGrid, 128, 18 * 100 * sizeof(float)>>>(
        off, csrc, eac, W1e, a1, xl1, xr1, c1, out1);

    // --- layer 2: (100 -> 200), fused GAT ---
    {
        dim3 g((200 + 63) / 64, (NN + 63) / 64);
        k_gemm<<<g, 256>>>(out1, W2l, b2l, xl2, NN, 100, 200, 0);
        k_gemm<<<g, 256>>>(out1, W2r, b2r, xr2, NN, 100, 200, 0);
    }
    k_gat<200, 7><<<gatGrid, 128, 18 * 200 * sizeof(float)>>>(
        off, csrc, eac, W2e, a2, xl2, xr2, c2, out2);

    // --- mean pool h2 FIRST (linear commutes with mean), then tiny 200->400 ---
    cudaMemsetAsync(pool2, 0, GG * 200 * sizeof(float));
    cudaMemsetAsync(gcnt, 0, GG * sizeof(float));
    k_pool<<<(NN * 200 + T - 1) / T, T>>>(out2, bid, pool2, gcnt);
    k_pooldiv<<<(GG * 200 + T - 1) / T, T>>>(pool2, gcnt);
    {
        dim3 g((400 + 63) / 64, (GG + 63) / 64);
        k_gemm<<<g, 256>>>(pool2, W3, b3, pool3, GG, 200, 400, 0);
    }

    // --- FFN head ---
    {
        dim3 g((200 + 63) / 64, (GG + 63) / 64);
        k_gemm<<<g, 256>>>(pool3, F1, bf1, y1, GG, 400, 200, 1);
    }
    {
        dim3 g((100 + 63) / 64, (GG + 63) / 64);
        k_gemm<<<g, 256>>>(y1, F2, bf2, y2, GG, 200, 100, 1);
    }
    {
        dim3 g((100 + 63) / 64, (GG + 63) / 64);
        k_gemm<<<g, 256>>>(y2, F3, bf3, (float*)d_out, GG, 100, 100, 0);
    }
}

// round 7
// speedup vs baseline: 2.6188x; 1.1521x over previous
#include <cuda_runtime.h>
#include <math.h>

#define NN 50000
#define EE 1600000
#define E2T (EE + NN)
#define GG 512
#define NEG 0.2f

// ---------------- scratch (allocation-free: __device__ globals) ----------------
__device__ float g_xlr1[(size_t)NN * 200];  // layer1 [xl | xr] interleaved per row
__device__ float g_out1[(size_t)NN * 100];
__device__ float g_xlr2[(size_t)NN * 400];  // layer2 [xl | xr]
__device__ float g_out2[(size_t)NN * 200];
__device__ float g_eac[(size_t)E2T * 18];   // edge attrs, CSR-ordered
__device__ int   g_cnt[NN];
__device__ int   g_off[NN + 1];
__device__ int   g_cur[NN];
__device__ int   g_csrc[E2T];
__device__ int   g_pos[E2T];
__device__ float g_pool2[GG * 200];
__device__ float g_pool3[GG * 400];
__device__ float g_y1[GG * 200];
__device__ float g_y2[GG * 100];

// ---------------- CSR build ----------------
__global__ void k_hist(const int* __restrict__ ei, int* __restrict__ cnt) {
    int i = blockIdx.x * blockDim.x + threadIdx.x;
    if (i < EE) atomicAdd(&cnt[ei[EE + i]], 1);
    else if (i < EE + NN) atomicAdd(&cnt[i - EE], 1);
}

__global__ void k_scan(const int* __restrict__ cnt, int* __restrict__ off) {
    __shared__ int ssum[1024];
    int t = threadIdx.x;
    const int NPT = (NN + 1023) / 1024;
    int base = t * NPT;
    int local = 0;
    for (int i = 0; i < NPT; i++)
        if (base + i < NN) local += cnt[base + i];
    ssum[t] = local;
    __syncthreads();
    for (int o = 1; o < 1024; o <<= 1) {
        int v = (t >= o) ? ssum[t - o] : 0;
        __syncthreads();
        ssum[t] += v;
        __syncthreads();
    }
    int run = ssum[t] - local;
    for (int i = 0; i < NPT; i++) {
        int idx = base + i;
        if (idx < NN) { off[idx] = run; run += cnt[idx]; }
    }
    if (t == 1023) off[NN] = run;
}

__global__ void k_scatter(const int* __restrict__ ei, const int* __restrict__ off,
                          int* __restrict__ cur, int* __restrict__ csrc,
                          int* __restrict__ pos) {
    int e = blockIdx.x * blockDim.x + threadIdx.x;
    if (e >= E2T) return;
    int sn, dn;
    if (e < EE) { sn = ei[e]; dn = ei[EE + e]; }
    else        { sn = e - EE; dn = sn; }
    int p = off[dn] + atomicAdd(&cur[dn], 1);
    csrc[p] = sn;
    pos[e] = p;
}

__global__ void k_eagather(const float* __restrict__ ea, const int* __restrict__ pos,
                           float* __restrict__ eac) {
    int i = blockIdx.x * blockDim.x + threadIdx.x;
    if (i >= EE * 18) return;
    int e = i / 18, k = i - e * 18;
    eac[(size_t)pos[e] * 18 + k] = ea[i];
}

__global__ void k_loopattr(const int* __restrict__ off, const int* __restrict__ pos,
                           float* __restrict__ eac) {
    int n = (blockIdx.x * blockDim.x + threadIdx.x) >> 5;
    int lane = threadIdx.x & 31;
    if (n >= NN) return;
    int start = off[n], end = off[n + 1];
    int selfpos = pos[EE + n];
    float acc = 0.f;
    if (lane < 18)
        for (int i = start; i < end; i++)
            if (i != selfpos) acc += eac[(size_t)i * 18 + lane];
    float deg = (float)(end - start - 1);
    if (lane < 18) eac[(size_t)selfpos * 18 + lane] = acc / fmaxf(deg, 1.0f);
}

// ---------------- register-tiled GEMM: C = [relu](A @ B + bias) ----------------
__global__ void k_gemm(const float* __restrict__ A, const float* __restrict__ B,
                       const float* __restrict__ bias, float* __restrict__ Cm,
                       int M, int K, int N, int relu) {
    __shared__ float As[16][64];
    __shared__ float Bs[16][64];
    int bm = blockIdx.y * 64, bn = blockIdx.x * 64;
    int tid = threadIdx.x;
    int tx = tid & 15, ty = tid >> 4;
    float acc[4][4];
#pragma unroll
    for (int r = 0; r < 4; r++)
#pragma unroll
        for (int c = 0; c < 4; c++) acc[r][c] = 0.f;
    for (int k0 = 0; k0 < K; k0 += 16) {
        for (int l = tid; l < 64 * 16; l += 256) {
            int r = l >> 4, kk = l & 15;
            As[kk][r] = (bm + r < M && k0 + kk < K) ? A[(size_t)(bm + r) * K + k0 + kk] : 0.f;
        }
        for (int l = tid; l < 16 * 64; l += 256) {
            int kk = l >> 6, c = l & 63;
            Bs[kk][c] = (k0 + kk < K && bn + c < N) ? B[(size_t)(k0 + kk) * N + bn + c] : 0.f;
        }
        __syncthreads();
#pragma unroll
        for (int kk = 0; kk < 16; kk++) {
            float av[4], bv[4];
#pragma unroll
            for (int r = 0; r < 4; r++) av[r] = As[kk][ty * 4 + r];
#pragma unroll
            for (int c = 0; c < 4; c++) bv[c] = Bs[kk][tx * 4 + c];
#pragma unroll
            for (int r = 0; r < 4; r++)
#pragma unroll
                for (int c = 0; c < 4; c++) acc[r][c] += av[r] * bv[c];
        }
        __syncthreads();
    }
#pragma unroll
    for (int r = 0; r < 4; r++) {
        int row = bm + ty * 4 + r;
        if (row >= M) continue;
#pragma unroll
        for (int c = 0; c < 4; c++) {
            int col = bn + tx * 4 + c;
            if (col < N) {
                float v = acc[r][c] + bias[col];
                Cm[(size_t)row * N + col] = relu ? fmaxf(v, 0.f) : v;
            }
        }
    }
}

// ---------------- fused xl/xr GEMM: out[M, 2C] = A @ [Bl | Br] + [bl | br] ------
__global__ void k_gemm2(const float* __restrict__ A,
                        const float* __restrict__ Bl, const float* __restrict__ Br,
                        const float* __restrict__ bl, const float* __restrict__ br,
                        float* __restrict__ Cm, int M, int K, int C) {
    __shared__ float As[16][64];
    __shared__ float Bs[16][64];
    int N = 2 * C;
    int bm = blockIdx.y * 64, bn = blockIdx.x * 64;
    int tid = threadIdx.x;
    int tx = tid & 15, ty = tid >> 4;
    float acc[4][4];
#pragma unroll
    for (int r = 0; r < 4; r++)
#pragma unroll
        for (int c = 0; c < 4; c++) acc[r][c] = 0.f;
    for (int k0 = 0; k0 < K; k0 += 16) {
        for (int l = tid; l < 64 * 16; l += 256) {
            int r = l >> 4, kk = l & 15;
            As[kk][r] = (bm + r < M && k0 + kk < K) ? A[(size_t)(bm + r) * K + k0 + kk] : 0.f;
        }
        for (int l = tid; l < 16 * 64; l += 256) {
            int kk = l >> 6, c = l & 63;
            int cg = bn + c;
            float v = 0.f;
            if (k0 + kk < K && cg < N)
                v = (cg < C) ? Bl[(size_t)(k0 + kk) * C + cg]
                             : Br[(size_t)(k0 + kk) * C + cg - C];
            Bs[kk][c] = v;
        }
        __syncthreads();
#pragma unroll
        for (int kk = 0; kk < 16; kk++) {
            float av[4], bv[4];
#pragma unroll
            for (int r = 0; r < 4; r++) av[r] = As[kk][ty * 4 + r];
#pragma unroll
            for (int c = 0; c < 4; c++) bv[c] = Bs[kk][tx * 4 + c];
#pragma unroll
            for (int r = 0; r < 4; r++)
#pragma unroll
                for (int c = 0; c < 4; c++) acc[r][c] += av[r] * bv[c];
        }
        __syncthreads();
    }
#pragma unroll
    for (int r = 0; r < 4; r++) {
        int row = bm + ty * 4 + r;
        if (row >= M) continue;
#pragma unroll
        for (int c = 0; c < 4; c++) {
            int col = bn + tx * 4 + c;
            if (col < N) {
                float bb = (col < C) ? bl[col] : br[col - C];
                Cm[(size_t)row * N + col] = acc[r][c] + bb;
            }
        }
    }
}

// ---------------- fused GATv2: 4 edges/iter, shuffle-in-k-loop ----------------
// xlr row layout: [xl(0..C-1) | xr(0..C-1)], stride 2C
template <int C, int NC>
__global__ __launch_bounds__(256)
void k_gat(const int* __restrict__ off, const int* __restrict__ csrc,
           const float* __restrict__ eac, const float* __restrict__ We,
           const float* __restrict__ av, const float* __restrict__ xlr,
           const float* __restrict__ bias, float* __restrict__ out) {
    extern __shared__ float sWe[];  // [18][C]
    for (int idx = threadIdx.x; idx < 18 * C; idx += blockDim.x) sWe[idx] = We[idx];
    __syncthreads();

    int n = (blockIdx.x * blockDim.x + threadIdx.x) >> 5;
    int lane = threadIdx.x & 31;
    if (n >= NN) return;

    float avr[NC], xrr[NC], acc[NC];
#pragma unroll
    for (int j = 0; j < NC; j++) {
        int c = lane + 32 * j;
        avr[j] = (c < C) ? av[c] : 0.f;
        xrr[j] = (c < C) ? xlr[(size_t)n * 2 * C + C + c] : 0.f;
        acc[j] = 0.f;
    }
    float m = -3.0e38f, z = 0.f;
    int start = off[n], end = off[n + 1];
    int i = start;

    for (; i + 3 < end; i += 4) {
        int s0 = csrc[i], s1 = csrc[i + 1], s2 = csrc[i + 2], s3 = csrc[i + 3];
        float a0 = 0.f, a1 = 0.f, a2 = 0.f, a3 = 0.f;
        if (lane < 18) {
            const float* ep = eac + (size_t)i * 18;
            a0 = ep[lane]; a1 = ep[18 + lane]; a2 = ep[36 + lane]; a3 = ep[54 + lane];
        }
        const float* p0 = xlr + (size_t)s0 * 2 * C;
        const float* p1 = xlr + (size_t)s1 * 2 * C;
        const float* p2 = xlr + (size_t)s2 * 2 * C;
        const float* p3 = xlr + (size_t)s3 * 2 * C;
        float x0[NC], x1[NC], x2[NC], x3[NC];
        float v0[NC], v1[NC], v2[NC], v3[NC];
#pragma unroll
        for (int j = 0; j < NC; j++) {
            int c = lane + 32 * j;
            bool ok = (c < C);
            x0[j] = ok ? p0[c] : 0.f;  x1[j] = ok ? p1[c] : 0.f;
            x2[j] = ok ? p2[c] : 0.f;  x3[j] = ok ? p3[c] : 0.f;
            v0[j] = x0[j] + xrr[j];    v1[j] = x1[j] + xrr[j];
            v2[j] = x2[j] + xrr[j];    v3[j] = x3[j] + xrr[j];
        }
#pragma unroll
        for (int k = 0; k < 18; k++) {
            float e0 = __shfl_sync(0xffffffffu, a0, k);
            float e1 = __shfl_sync(0xffffffffu, a1, k);
            float e2 = __shfl_sync(0xffffffffu, a2, k);
            float e3 = __shfl_sync(0xffffffffu, a3, k);
#pragma unroll
            for (int j = 0; j < NC; j++) {
                int c = lane + 32 * j;
                float w_ = (c < C) ? sWe[k * C + c] : 0.f;
                v0[j] += e0 * w_; v1[j] += e1 * w_;
                v2[j] += e2 * w_; v3[j] += e3 * w_;
            }
        }
        float sc0 = 0.f, sc1 = 0.f, sc2 = 0.f, sc3 = 0.f;
#pragma unroll
        for (int j = 0; j < NC; j++) {
            float t;
            t = v0[j]; sc0 += avr[j] * ((t > 0.f) ? t : NEG * t);
            t = v1[j]; sc1 += avr[j] * ((t > 0.f) ? t : NEG * t);
            t = v2[j]; sc2 += avr[j] * ((t > 0.f) ? t : NEG * t);
            t = v3[j]; sc3 += avr[j] * ((t > 0.f) ? t : NEG * t);
        }
#pragma unroll
        for (int o = 16; o; o >>= 1) {
            sc0 += __shfl_xor_sync(0xffffffffu, sc0, o);
            sc1 += __shfl_xor_sync(0xffffffffu, sc1, o);
            sc2 += __shfl_xor_sync(0xffffffffu, sc2, o);
            sc3 += __shfl_xor_sync(0xffffffffu, sc3, o);
        }
        float newm = fmaxf(fmaxf(m, fmaxf(sc0, sc1)), fmaxf(sc2, sc3));
        float scale = __expf(m - newm);
        float w0 = __expf(sc0 - newm), w1 = __expf(sc1 - newm);
        float w2 = __expf(sc2 - newm), w3 = __expf(sc3 - newm);
        z = z * scale + w0 + w1 + w2 + w3;
#pragma unroll
        for (int j = 0; j < NC; j++)
            acc[j] = acc[j] * scale + w0 * x0[j] + w1 * x1[j] + w2 * x2[j] + w3 * x3[j];
        m = newm;
    }
    for (; i < end; i++) {   // tail 0-3 edges
        int s0 = csrc[i];
        float a0 = 0.f;
        if (lane < 18) a0 = eac[(size_t)i * 18 + lane];
        const float* p0 = xlr + (size_t)s0 * 2 * C;
        float x0[NC], v0[NC];
#pragma unroll
        for (int j = 0; j < NC; j++) {
            int c = lane + 32 * j;
            x0[j] = (c < C) ? p0[c] : 0.f;
            v0[j] = x0[j] + xrr[j];
        }
#pragma unroll
        for (int k = 0; k < 18; k++) {
            float e0 = __shfl_sync(0xffffffffu, a0, k);
#pragma unroll
            for (int j = 0; j < NC; j++) {
                int c = lane + 32 * j;
                float w_ = (c < C) ? sWe[k * C + c] : 0.f;
                v0[j] += e0 * w_;
            }
        }
        float sc0 = 0.f;
#pragma unroll
        for (int j = 0; j < NC; j++) {
            float t = v0[j]; sc0 += avr[j] * ((t > 0.f) ? t : NEG * t);
        }
#pragma unroll
        for (int o = 16; o; o >>= 1) sc0 += __shfl_xor_sync(0xffffffffu, sc0, o);
        float newm = fmaxf(m, sc0);
        float scale = __expf(m - newm);
        float w0 = __expf(sc0 - newm);
        z = z * scale + w0;
#pragma unroll
        for (int j = 0; j < NC; j++) acc[j] = acc[j] * scale + w0 * x0[j];
        m = newm;
    }
    float invz = __fdividef(1.0f, z);
#pragma unroll
    for (int j = 0; j < NC; j++) {
        int c = lane + 32 * j;
        if (c < C) out[(size_t)n * C + c] = fmaxf(acc[j] * invz + bias[c], 0.f);
    }
}

// ---------------- atomic-free mean pool (batch_ids sorted): block per graph ------
__global__ void k_pool(const float* __restrict__ h, const int* __restrict__ bid,
                       float* __restrict__ pool) {
    int g = blockIdx.x;
    __shared__ int slo, shi;
    if (threadIdx.x == 0) {
        // lower_bound(g) and lower_bound(g+1) over sorted bid[0..NN)
        int lo = 0, hi = NN;
        while (lo < hi) { int mid = (lo + hi) >> 1; if (bid[mid] < g) lo = mid + 1; else hi = mid; }
        slo = lo;
        int lo2 = lo; hi = NN;
        while (lo2 < hi) { int mid = (lo2 + hi) >> 1; if (bid[mid] < g + 1) lo2 = mid + 1; else hi = mid; }
        shi = lo2;
    }
    __syncthreads();
    int lo = slo, hi = shi;
    float inv = 1.0f / (float)max(hi - lo, 1);
    for (int c = threadIdx.x; c < 200; c += blockDim.x) {
        float sum = 0.f;
        for (int nn = lo; nn < hi; nn++) sum += h[(size_t)nn * 200 + c];
        pool[g * 200 + c] = sum * inv;
    }
}

// ---------------- launch ----------------
extern "C" void kernel_launch(void* const* d_in, const int* in_sizes, int n_in,
                              void* d_out, int out_size) {
    const float* x   = (const float*)d_in[0];
    const int*   ei  = (const int*)d_in[1];
    const float* ea  = (const float*)d_in[2];
    const int*   bid = (const int*)d_in[3];
    const float* W1l = (const float*)d_in[4];
    const float* b1l = (const float*)d_in[5];
    const float* W1r = (const float*)d_in[6];
    const float* b1r = (const float*)d_in[7];
    const float* W1e = (const float*)d_in[8];
    const float* a1  = (const float*)d_in[9];
    const float* c1  = (const float*)d_in[10];
    const float* W2l = (const float*)d_in[11];
    const float* b2l = (const float*)d_in[12];
    const float* W2r = (const float*)d_in[13];
    const float* b2r = (const float*)d_in[14];
    const float* W2e = (const float*)d_in[15];
    const float* a2  = (const float*)d_in[16];
    const float* c2  = (const float*)d_in[17];
    const float* W3  = (const float*)d_in[18];
    const float* b3  = (const float*)d_in[19];
    const float* F1  = (const float*)d_in[20];
    const float* bf1 = (const float*)d_in[21];
    const float* F2  = (const float*)d_in[22];
    const float* bf2 = (const float*)d_in[23];
    const float* F3  = (const float*)d_in[24];
    const float* bf3 = (const float*)d_in[25];

    float *xlr1, *out1, *xlr2, *out2, *eac, *pool2, *pool3, *y1, *y2;
    int *cnt, *off, *cur, *csrc, *pos;
    cudaGetSymbolAddress((void**)&xlr1,  g_xlr1);
    cudaGetSymbolAddress((void**)&out1,  g_out1);
    cudaGetSymbolAddress((void**)&xlr2,  g_xlr2);
    cudaGetSymbolAddress((void**)&out2,  g_out2);
    cudaGetSymbolAddress((void**)&eac,   g_eac);
    cudaGetSymbolAddress((void**)&cnt,   g_cnt);
    cudaGetSymbolAddress((void**)&off,   g_off);
    cudaGetSymbolAddress((void**)&cur,   g_cur);
    cudaGetSymbolAddress((void**)&csrc,  g_csrc);
    cudaGetSymbolAddress((void**)&pos,   g_pos);
    cudaGetSymbolAddress((void**)&pool2, g_pool2);
    cudaGetSymbolAddress((void**)&pool3, g_pool3);
    cudaGetSymbolAddress((void**)&y1,    g_y1);
    cudaGetSymbolAddress((void**)&y2,    g_y2);

    const int T = 256;
    const int gatGrid = (NN + 7) / 8;        // warp per node, 8 warps / block
    const int nodeWarpGrid = (NN + 7) / 8;

    // --- CSR by dst + CSR-ordered edge attrs ---
    cudaMemsetAsync(cnt, 0, NN * sizeof(int));
    cudaMemsetAsync(cur, 0, NN * sizeof(int));
    k_hist<<<(EE + NN + T - 1) / T, T>>>(ei, cnt);
    k_scan<<<1, 1024>>>(cnt, off);
    k_scatter<<<(E2T + T - 1) / T, T>>>(ei, off, cur, csrc, pos);
    k_eagather<<<(EE * 18 + T - 1) / T, T>>>(ea, pos, eac);
    k_loopattr<<<nodeWarpGrid, T>>>(off, pos, eac);

    // --- layer 1 ---
    {
        dim3 g((200 + 63) / 64, (NN + 63) / 64);
        k_gemm2<<<g, 256>>>(x, W1l, W1r, b1l, b1r, xlr1, NN, 16, 100);
    }
    k_gat<100, 4><<<gatGrid, 256, 18 * 100 * sizeof(float)>>>(
        off, csrc, eac, W1e, a1, xlr1, c1, out1);

    // --- layer 2 ---
    {
        dim3 g((400 + 63) / 64, (NN + 63) / 64);
        k_gemm2<<<g, 256>>>(out1, W2l, W2r, b2l, b2r, xlr2, NN, 100, 200);
    }
    k_gat<200, 7><<<gatGrid, 256, 18 * 200 * sizeof(float)>>>(
        off, csrc, eac, W2e, a2, xlr2, c2, out2);

    // --- mean pool (sorted batch ids, atomic-free), then tiny 200->400 ---
    k_pool<<<GG, 256>>>(out2, bid, pool2);
    {
        dim3 g((400 + 63) / 64, (GG + 63) / 64);
        k_gemm<<<g, 256>>>(pool2, W3, b3, pool3, GG, 200, 400, 0);
    }

    // --- FFN head ---
    {
        dim3 g((200 + 63) / 64, (GG + 63) / 64);
        k_gemm<<<g, 256>>>(pool3, F1, bf1, y1, GG, 400, 200, 1);
    }
    {
        dim3 g((100 + 63) / 64, (GG + 63) / 64);
        k_gemm<<<g, 256>>>(y1, F2, bf2, y2, GG, 200, 100, 1);
    }
    {
        dim3 g((100 + 63) / 64, (GG + 63) / 64);
        k_gemm<<<g, 256>>>(y2, F3, bf3, (float*)d_out, GG, 100, 100, 0);
    }
}

// round 8
// speedup vs baseline: 2.6468x; 1.0107x over previous
#include <cuda_runtime.h>
#include <mma.h>
#include <math.h>

using namespace nvcuda;

#define NN 50000
#define EE 1600000
#define E2T (EE + NN)
#define GG 512
#define NEG 0.2f
#define EACW 24      // padded edge-attr row stride (96B, sector aligned)
#define DMAX 1024    // degree clamp for counting sort

// ---------------- scratch ----------------
__device__ float g_xlr1[(size_t)NN * 200];
__device__ float g_out1[(size_t)NN * 100];
__device__ float g_xlr2[(size_t)NN * 400];
__device__ float g_out2[(size_t)NN * 200];
__device__ float g_eac[(size_t)E2T * EACW];
__device__ int   g_cnt[NN];
__device__ int   g_off[NN + 1];
__device__ int   g_cur[NN];
__device__ int   g_csrc[E2T];
__device__ int   g_pos[E2T];
__device__ int   g_dh[DMAX];
__device__ int   g_doff[DMAX];
__device__ int   g_dcur[DMAX];
__device__ int   g_perm[NN];
__device__ float g_pool2[GG * 200];
__device__ float g_pool3[GG * 400];
__device__ float g_y1[GG * 200];
__device__ float g_y2[GG * 100];

// ---------------- CSR build ----------------
__global__ void k_hist(const int* __restrict__ ei, int* __restrict__ cnt) {
    int i = blockIdx.x * blockDim.x + threadIdx.x;
    if (i < EE) atomicAdd(&cnt[ei[EE + i]], 1);
    else if (i < EE + NN) atomicAdd(&cnt[i - EE], 1);
}

__global__ void k_scan(const int* __restrict__ cnt, int* __restrict__ off) {
    __shared__ int ssum[1024];
    int t = threadIdx.x;
    const int NPT = (NN + 1023) / 1024;
    int base = t * NPT;
    int local = 0;
    for (int i = 0; i < NPT; i++)
        if (base + i < NN) local += cnt[base + i];
    ssum[t] = local;
    __syncthreads();
    for (int o = 1; o < 1024; o <<= 1) {
        int v = (t >= o) ? ssum[t - o] : 0;
        __syncthreads();
        ssum[t] += v;
        __syncthreads();
    }
    int run = ssum[t] - local;
    for (int i = 0; i < NPT; i++) {
        int idx = base + i;
        if (idx < NN) { off[idx] = run; run += cnt[idx]; }
    }
    if (t == 1023) off[NN] = run;
}

__global__ void k_scatter(const int* __restrict__ ei, const int* __restrict__ off,
                          int* __restrict__ cur, int* __restrict__ csrc,
                          int* __restrict__ pos) {
    int e = blockIdx.x * blockDim.x + threadIdx.x;
    if (e >= E2T) return;
    int sn, dn;
    if (e < EE) { sn = ei[e]; dn = ei[EE + e]; }
    else        { sn = e - EE; dn = sn; }
    int p = off[dn] + atomicAdd(&cur[dn], 1);
    csrc[p] = sn;
    pos[e] = p;
}

// vectorized gather of edge attrs into padded CSR rows (float2, 9 per edge)
__global__ void k_eagather(const float* __restrict__ ea, const int* __restrict__ pos,
                           float* __restrict__ eac) {
    int i = blockIdx.x * blockDim.x + threadIdx.x;
    if (i >= EE * 9) return;
    int e = i / 9, k = i - e * 9;
    float2 v = ((const float2*)ea)[i];
    ((float2*)eac)[(size_t)pos[e] * (EACW / 2) + k] = v;
}

__global__ void k_loopattr(const int* __restrict__ off, const int* __restrict__ pos,
                           float* __restrict__ eac) {
    int n = (blockIdx.x * blockDim.x + threadIdx.x) >> 5;
    int lane = threadIdx.x & 31;
    if (n >= NN) return;
    int start = off[n], end = off[n + 1];
    int selfpos = pos[EE + n];
    float acc = 0.f;
    if (lane < 18)
        for (int i = start; i < end; i++)
            if (i != selfpos) acc += eac[(size_t)i * EACW + lane];
    float deg = (float)(end - start - 1);
    if (lane < 18) eac[(size_t)selfpos * EACW + lane] = acc / fmaxf(deg, 1.0f);
}

// ---------------- degree counting-sort (descending) ----------------
__global__ void k_deghist(const int* __restrict__ off, int* __restrict__ dh) {
    int n = blockIdx.x * blockDim.x + threadIdx.x;
    if (n >= NN) return;
    int d = min(off[n + 1] - off[n], DMAX - 1);
    atomicAdd(&dh[d], 1);
}

// descending-degree offsets: doff[d] = sum_{d' > d} dh[d']
__global__ void k_dscan(const int* __restrict__ dh, int* __restrict__ doff) {
    __shared__ int s[DMAX];
    int t = threadIdx.x;
    s[t] = dh[DMAX - 1 - t];       // reversed
    __syncthreads();
    for (int o = 1; o < DMAX; o <<= 1) {
        int v = (t >= o) ? s[t - o] : 0;
        __syncthreads();
        s[t] += v;
        __syncthreads();
    }
    // exclusive prefix of reversed = total of strictly-larger degrees
    int excl = s[t] - dh[DMAX - 1 - t];
    doff[DMAX - 1 - t] = excl;
}

__global__ void k_dscatter(const int* __restrict__ off, const int* __restrict__ doff,
                           int* __restrict__ dcur, int* __restrict__ perm) {
    int n = blockIdx.x * blockDim.x + threadIdx.x;
    if (n >= NN) return;
    int d = min(off[n + 1] - off[n], DMAX - 1);
    int p = doff[d] + atomicAdd(&dcur[d], 1);
    perm[p] = n;
}

// ---------------- SIMT GEMM (small matrices: FFN head) ----------------
__global__ void k_gemm(const float* __restrict__ A, const float* __restrict__ B,
                       const float* __restrict__ bias, float* __restrict__ Cm,
                       int M, int K, int N, int relu) {
    __shared__ float As[16][64];
    __shared__ float Bs[16][64];
    int bm = blockIdx.y * 64, bn = blockIdx.x * 64;
    int tid = threadIdx.x;
    int tx = tid & 15, ty = tid >> 4;
    float acc[4][4];
#pragma unroll
    for (int r = 0; r < 4; r++)
#pragma unroll
        for (int c = 0; c < 4; c++) acc[r][c] = 0.f;
    for (int k0 = 0; k0 < K; k0 += 16) {
        for (int l = tid; l < 64 * 16; l += 256) {
            int r = l >> 4, kk = l & 15;
            As[kk][r] = (bm + r < M && k0 + kk < K) ? A[(size_t)(bm + r) * K + k0 + kk] : 0.f;
        }
        for (int l = tid; l < 16 * 64; l += 256) {
            int kk = l >> 6, c = l & 63;
            Bs[kk][c] = (k0 + kk < K && bn + c < N) ? B[(size_t)(k0 + kk) * N + bn + c] : 0.f;
        }
        __syncthreads();
#pragma unroll
        for (int kk = 0; kk < 16; kk++) {
            float av[4], bv[4];
#pragma unroll
            for (int r = 0; r < 4; r++) av[r] = As[kk][ty * 4 + r];
#pragma unroll
            for (int c = 0; c < 4; c++) bv[c] = Bs[kk][tx * 4 + c];
#pragma unroll
            for (int r = 0; r < 4; r++)
#pragma unroll
                for (int c = 0; c < 4; c++) acc[r][c] += av[r] * bv[c];
        }
        __syncthreads();
    }
#pragma unroll
    for (int r = 0; r < 4; r++) {
        int row = bm + ty * 4 + r;
        if (row >= M) continue;
#pragma unroll
        for (int c = 0; c < 4; c++) {
            int col = bn + tx * 4 + c;
            if (col < N) {
                float v = acc[r][c] + bias[col];
                Cm[(size_t)row * N + col] = relu ? fmaxf(v, 0.f) : v;
            }
        }
    }
}

// ---------------- TF32 wmma fused xl/xr GEMM: out[M, 2C] = A @ [Bl|Br] + [bl|br] ---
__global__ __launch_bounds__(256)
void k_gemm2_tc(const float* __restrict__ A,
                const float* __restrict__ Bl, const float* __restrict__ Br,
                const float* __restrict__ bl, const float* __restrict__ br,
                float* __restrict__ Cm, int M, int K, int C) {
    __shared__ float As[64 * 16];       // [64][16]
    __shared__ float Bs[16 * 72];       // [16][72] padded
    __shared__ float Cs[64 * 68];       // [64][68] padded
    const int N = 2 * C;
    int bm = blockIdx.y * 64, bn = blockIdx.x * 64;
    int tid = threadIdx.x;
    int w = tid >> 5;
    int wy = w >> 1, wx = w & 1;        // warp computes rows wy*16..+16, cols wx*32..+32

    wmma::fragment<wmma::accumulator, 16, 16, 8, float> acc[2];
    wmma::fill_fragment(acc[0], 0.f);
    wmma::fill_fragment(acc[1], 0.f);

    for (int k0 = 0; k0 < K; k0 += 16) {
        for (int l = tid; l < 64 * 16; l += 256) {
            int r = l >> 4, kk = l & 15;
            As[r * 16 + kk] = (bm + r < M && k0 + kk < K) ? A[(size_t)(bm + r) * K + k0 + kk] : 0.f;
        }
        for (int l = tid; l < 16 * 64; l += 256) {
            int kk = l >> 6, c = l & 63;
            int cg = bn + c;
            float v = 0.f;
            if (k0 + kk < K && cg < N)
                v = (cg < C) ? Bl[(size_t)(k0 + kk) * C + cg]
                             : Br[(size_t)(k0 + kk) * C + cg - C];
            Bs[kk * 72 + c] = v;
        }
        __syncthreads();
#pragma unroll
        for (int k8 = 0; k8 < 16; k8 += 8) {
            wmma::fragment<wmma::matrix_a, 16, 16, 8, wmma::precision::tf32, wmma::row_major> af;
            wmma::load_matrix_sync(af, &As[(wy * 16) * 16 + k8], 16);
#pragma unroll
            for (int i = 0; i < af.num_elements; i++) af.x[i] = wmma::__float_to_tf32(af.x[i]);
#pragma unroll
            for (int t = 0; t < 2; t++) {
                wmma::fragment<wmma::matrix_b, 16, 16, 8, wmma::precision::tf32, wmma::row_major> bf;
                wmma::load_matrix_sync(bf, &Bs[k8 * 72 + wx * 32 + t * 16], 72);
#pragma unroll
                for (int i = 0; i < bf.num_elements; i++) bf.x[i] = wmma::__float_to_tf32(bf.x[i]);
                wmma::mma_sync(acc[t], af, bf, acc[t]);
            }
        }
        __syncthreads();
    }
#pragma unroll
    for (int t = 0; t < 2; t++)
        wmma::store_matrix_sync(&Cs[(wy * 16) * 68 + wx * 32 + t * 16], acc[t], 68, wmma::mem_row_major);
    __syncthreads();
    for (int l = tid; l < 64 * 64; l += 256) {
        int r = l >> 6, c = l & 63;
        int row = bm + r, col = bn + c;
        if (row < M && col < N) {
            float bb = (col < C) ? bl[col] : br[col - C];
            Cm[(size_t)row * N + col] = Cs[r * 68 + c] + bb;
        }
    }
}

// ---------------- fused GATv2: U edges/iter, degree-sorted warp->node map --------
template <int C, int NC, int U>
__global__ __launch_bounds__(256)
void k_gat(const int* __restrict__ off, const int* __restrict__ csrc,
           const int* __restrict__ perm, const float* __restrict__ eac,
           const float* __restrict__ We, const float* __restrict__ av,
           const float* __restrict__ xlr, const float* __restrict__ bias,
           float* __restrict__ out) {
    extern __shared__ float sWe[];  // [18][C]
    for (int idx = threadIdx.x; idx < 18 * C; idx += blockDim.x) sWe[idx] = We[idx];
    __syncthreads();

    int wid = (blockIdx.x * blockDim.x + threadIdx.x) >> 5;
    int lane = threadIdx.x & 31;
    if (wid >= NN) return;
    int n = perm[wid];

    float avr[NC], xrr[NC], acc[NC];
#pragma unroll
    for (int j = 0; j < NC; j++) {
        int c = lane + 32 * j;
        avr[j] = (c < C) ? av[c] : 0.f;
        xrr[j] = (c < C) ? xlr[(size_t)n * 2 * C + C + c] : 0.f;
        acc[j] = 0.f;
    }
    float m = -3.0e38f, z = 0.f;
    int start = off[n], end = off[n + 1];
    int i = start;

    for (; i + U <= end; i += U) {
        int s[U];
        float av_[U];
#pragma unroll
        for (int u = 0; u < U; u++) {
            s[u] = csrc[i + u];
            av_[u] = (lane < 18) ? eac[(size_t)(i + u) * EACW + lane] : 0.f;
        }
        float xv[U][NC], vv[U][NC];
#pragma unroll
        for (int u = 0; u < U; u++) {
            const float* p = xlr + (size_t)s[u] * 2 * C;
#pragma unroll
            for (int j = 0; j < NC; j++) {
                int c = lane + 32 * j;
                xv[u][j] = (c < C) ? p[c] : 0.f;
                vv[u][j] = xv[u][j] + xrr[j];
            }
        }
#pragma unroll
        for (int k = 0; k < 18; k++) {
            float e[U];
#pragma unroll
            for (int u = 0; u < U; u++) e[u] = __shfl_sync(0xffffffffu, av_[u], k);
#pragma unroll
            for (int j = 0; j < NC; j++) {
                int c = lane + 32 * j;
                float w_ = (c < C) ? sWe[k * C + c] : 0.f;
#pragma unroll
                for (int u = 0; u < U; u++) vv[u][j] += e[u] * w_;
            }
        }
        float sc[U];
#pragma unroll
        for (int u = 0; u < U; u++) {
            float a_ = 0.f;
#pragma unroll
            for (int j = 0; j < NC; j++) {
                float t = vv[u][j];
                a_ += avr[j] * ((t > 0.f) ? t : NEG * t);
            }
            sc[u] = a_;
        }
#pragma unroll
        for (int o = 16; o; o >>= 1)
#pragma unroll
            for (int u = 0; u < U; u++) sc[u] += __shfl_xor_sync(0xffffffffu, sc[u], o);
        float newm = m;
#pragma unroll
        for (int u = 0; u < U; u++) newm = fmaxf(newm, sc[u]);
        float scale = __expf(m - newm);
        float wgt[U];
        float zadd = 0.f;
#pragma unroll
        for (int u = 0; u < U; u++) { wgt[u] = __expf(sc[u] - newm); zadd += wgt[u]; }
        z = z * scale + zadd;
#pragma unroll
        for (int j = 0; j < NC; j++) {
            float a_ = acc[j] * scale;
#pragma unroll
            for (int u = 0; u < U; u++) a_ += wgt[u] * xv[u][j];
            acc[j] = a_;
        }
        m = newm;
    }
    for (; i < end; i++) {   // tail
        int s0 = csrc[i];
        float a0 = (lane < 18) ? eac[(size_t)i * EACW + lane] : 0.f;
        const float* p0 = xlr + (size_t)s0 * 2 * C;
        float x0[NC], v0[NC];
#pragma unroll
        for (int j = 0; j < NC; j++) {
            int c = lane + 32 * j;
            x0[j] = (c < C) ? p0[c] : 0.f;
            v0[j] = x0[j] + xrr[j];
        }
#pragma unroll
        for (int k = 0; k < 18; k++) {
            float e0 = __shfl_sync(0xffffffffu, a0, k);
#pragma unroll
            for (int j = 0; j < NC; j++) {
                int c = lane + 32 * j;
                float w_ = (c < C) ? sWe[k * C + c] : 0.f;
                v0[j] += e0 * w_;
            }
        }
        float sc0 = 0.f;
#pragma unroll
        for (int j = 0; j < NC; j++) {
            float t = v0[j]; sc0 += avr[j] * ((t > 0.f) ? t : NEG * t);
        }
#pragma unroll
        for (int o = 16; o; o >>= 1) sc0 += __shfl_xor_sync(0xffffffffu, sc0, o);
        float newm = fmaxf(m, sc0);
        float scale = __expf(m - newm);
        float w0 = __expf(sc0 - newm);
        z = z * scale + w0;
#pragma unroll
        for (int j = 0; j < NC; j++) acc[j] = acc[j] * scale + w0 * x0[j];
        m = newm;
    }
    float invz = __fdividef(1.0f, z);
#pragma unroll
    for (int j = 0; j < NC; j++) {
        int c = lane + 32 * j;
        if (c < C) out[(size_t)n * C + c] = fmaxf(acc[j] * invz + bias[c], 0.f);
    }
}

// ---------------- atomic-free mean pool (batch_ids sorted) ----------------
__global__ void k_pool(const float* __restrict__ h, const int* __restrict__ bid,
                       float* __restrict__ pool) {
    int g = blockIdx.x;
    __shared__ int slo, shi;
    if (threadIdx.x == 0) {
        int lo = 0, hi = NN;
        while (lo < hi) { int mid = (lo + hi) >> 1; if (bid[mid] < g) lo = mid + 1; else hi = mid; }
        slo = lo;
        int lo2 = lo; hi = NN;
        while (lo2 < hi) { int mid = (lo2 + hi) >> 1; if (bid[mid] < g + 1) lo2 = mid + 1; else hi = mid; }
        shi = lo2;
    }
    __syncthreads();
    int lo = slo, hi = shi;
    float inv = 1.0f / (float)max(hi - lo, 1);
    for (int c = threadIdx.x; c < 200; c += blockDim.x) {
        float sum = 0.f;
        for (int nn = lo; nn < hi; nn++) sum += h[(size_t)nn * 200 + c];
        pool[g * 200 + c] = sum * inv;
    }
}

// ---------------- launch ----------------
extern "C" void kernel_launch(void* const* d_in, const int* in_sizes, int n_in,
                              void* d_out, int out_size) {
    const float* x   = (const float*)d_in[0];
    const int*   ei  = (const int*)d_in[1];
    const float* ea  = (const float*)d_in[2];
    const int*   bid = (const int*)d_in[3];
    const float* W1l = (const float*)d_in[4];
    const float* b1l = (const float*)d_in[5];
    const float* W1r = (const float*)d_in[6];
    const float* b1r = (const float*)d_in[7];
    const float* W1e = (const float*)d_in[8];
    const float* a1  = (const float*)d_in[9];
    const float* c1  = (const float*)d_in[10];
    const float* W2l = (const float*)d_in[11];
    const float* b2l = (const float*)d_in[12];
    const float* W2r = (const float*)d_in[13];
    const float* b2r = (const float*)d_in[14];
    const float* W2e = (const float*)d_in[15];
    const float* a2  = (const float*)d_in[16];
    const float* c2  = (const float*)d_in[17];
    const float* W3  = (const float*)d_in[18];
    const float* b3  = (const float*)d_in[19];
    const float* F1  = (const float*)d_in[20];
    const float* bf1 = (const float*)d_in[21];
    const float* F2  = (const float*)d_in[22];
    const float* bf2 = (const float*)d_in[23];
    const float* F3  = (const float*)d_in[24];
    const float* bf3 = (const float*)d_in[25];

    float *xlr1, *out1, *xlr2, *out2, *eac, *pool2, *pool3, *y1, *y2;
    int *cnt, *off, *cur, *csrc, *pos, *dh, *doff, *dcur, *perm;
    cudaGetSymbolAddress((void**)&xlr1,  g_xlr1);
    cudaGetSymbolAddress((void**)&out1,  g_out1);
    cudaGetSymbolAddress((void**)&xlr2,  g_xlr2);
    cudaGetSymbolAddress((void**)&out2,  g_out2);
    cudaGetSymbolAddress((void**)&eac,   g_eac);
    cudaGetSymbolAddress((void**)&cnt,   g_cnt);
    cudaGetSymbolAddress((void**)&off,   g_off);
    cudaGetSymbolAddress((void**)&cur,   g_cur);
    cudaGetSymbolAddress((void**)&csrc,  g_csrc);
    cudaGetSymbolAddress((void**)&pos,   g_pos);
    cudaGetSymbolAddress((void**)&dh,    g_dh);
    cudaGetSymbolAddress((void**)&doff,  g_doff);
    cudaGetSymbolAddress((void**)&dcur,  g_dcur);
    cudaGetSymbolAddress((void**)&perm,  g_perm);
    cudaGetSymbolAddress((void**)&pool2, g_pool2);
    cudaGetSymbolAddress((void**)&pool3, g_pool3);
    cudaGetSymbolAddress((void**)&y1,    g_y1);
    cudaGetSymbolAddress((void**)&y2,    g_y2);

    const int T = 256;
    const int gatGrid = (NN + 7) / 8;
    const int nodeWarpGrid = (NN + 7) / 8;

    // --- CSR by dst + padded CSR-ordered edge attrs + degree sort ---
    cudaMemsetAsync(cnt, 0, NN * sizeof(int));
    cudaMemsetAsync(cur, 0, NN * sizeof(int));
    cudaMemsetAsync(dh, 0, DMAX * sizeof(int));
    cudaMemsetAsync(dcur, 0, DMAX * sizeof(int));
    k_hist<<<(EE + NN + T - 1) / T, T>>>(ei, cnt);
    k_scan<<<1, 1024>>>(cnt, off);
    k_scatter<<<(E2T + T - 1) / T, T>>>(ei, off, cur, csrc, pos);
    k_eagather<<<(EE * 9 + T - 1) / T, T>>>(ea, pos, eac);
    k_loopattr<<<nodeWarpGrid, T>>>(off, pos, eac);
    k_deghist<<<(NN + T - 1) / T, T>>>(off, dh);
    k_dscan<<<1, DMAX>>>(dh, doff);
    k_dscatter<<<(NN + T - 1) / T, T>>>(off, doff, dcur, perm);

    // --- layer 1 ---
    {
        dim3 g((200 + 63) / 64, (NN + 63) / 64);
        k_gemm2_tc<<<g, 256>>>(x, W1l, W1r, b1l, b1r, xlr1, NN, 16, 100);
    }
    k_gat<100, 4, 8><<<gatGrid, 256, 18 * 100 * sizeof(float)>>>(
        off, csrc, perm, eac, W1e, a1, xlr1, c1, out1);

    // --- layer 2 ---
    {
        dim3 g((400 + 63) / 64, (NN + 63) / 64);
        k_gemm2_tc<<<g, 256>>>(out1, W2l, W2r, b2l, b2r, xlr2, NN, 100, 200);
    }
    k_gat<200, 7, 4><<<gatGrid, 256, 18 * 200 * sizeof(float)>>>(
        off, csrc, perm, eac, W2e, a2, xlr2, c2, out2);

    // --- mean pool, then 200->400 ---
    k_pool<<<GG, 256>>>(out2, bid, pool2);
    {
        dim3 g((400 + 63) / 64, (GG + 63) / 64);
        k_gemm<<<g, 256>>>(pool2, W3, b3, pool3, GG, 200, 400, 0);
    }

    // --- FFN head ---
    {
        dim3 g((200 + 63) / 64, (GG + 63) / 64);
        k_gemm<<<g, 256>>>(pool3, F1, bf1, y1, GG, 400, 200, 1);
    }
    {
        dim3 g((100 + 63) / 64, (GG + 63) / 64);
        k_gemm<<<g, 256>>>(y1, F2, bf2, y2, GG, 200, 100, 1);
    }
    {
        dim3 g((100 + 63) / 64, (GG + 63) / 64);
        k_gemm<<<g, 256>>>(y2, F3, bf3, (float*)d_out, GG, 100, 100, 0);
    }
}